// round 1
// baseline (speedup 1.0000x reference)
#include <cuda_runtime.h>
#include <math.h>
#include <stdint.h>

// ---------------------------------------------------------------------------
// ConformalMIL forward.  B=32, S=2048, D=512, H=16, HD=32, NCLS=2, K=19
// out = [logits (32*2) | attn (32*16*2*2048)]  fp32
// ---------------------------------------------------------------------------

#define Bb 32
#define Ss 2048
#define Dd 512
#define Mm (Bb * Ss)          // 65536
#define Hh 16
#define HDd 32
#define NCLS 2
#define KS 19

// scratch (static device allocations; no cudaMalloc allowed)
__device__ float g_ksum[Dd * KS];                    // summed wavelet kernel
__device__ float g_pos[(size_t)Mm * Dd];             // 128 MB
__device__ float g_y[(size_t)Mm * Dd];               // 128 MB  (y then xn in-place)
__device__ float g_kv[(size_t)Mm * 2 * Dd];          // 256 MB
__device__ float g_q[NCLS * Dd];
__device__ float g_o[Bb * NCLS * Dd];

// ---------------------------------------------------------------------------
// 1. wavelet kernels: ksum[d][t] = sum over 3 waves of mexican hat
// ---------------------------------------------------------------------------
__global__ void k_wavelet(const float* __restrict__ w1,
                          const float* __restrict__ w2,
                          const float* __restrict__ w3) {
    int d = blockIdx.x * blockDim.x + threadIdx.x;
    if (d >= Dd) return;
    const float C = 2.0f / (sqrtf(3.0f) * powf(3.14159265358979323846f, 0.25f));
    const float* ws[3] = {w1, w2, w3};
    float sc[3], sh[3], rs[3];
    #pragma unroll
    for (int w = 0; w < 3; w++) {
        sc[w] = ws[w][d];          // wave[0, d, 0] scale
        sh[w] = ws[w][Dd + d];     // wave[1, d, 0] shift
        rs[w] = rsqrtf(fabsf(sc[w]));
    }
    for (int t = 0; t < KS; t++) {
        float xt = (float)(t - 9);
        float acc = 0.f;
        #pragma unroll
        for (int w = 0; w < 3; w++) {
            float u = (xt - sh[w]) / sc[w];
            acc += C * (1.f - u * u) * expf(-0.5f * u * u) * rs[w];
        }
        g_ksum[d * KS + t] = acc;
    }
}

// ---------------------------------------------------------------------------
// 2. depthwise conv along S ('SAME', zero pad):
//    pos[b,s,d] = sum_t x[b, s+t-9, d] * ksum[d,t]
//    tile: 32 s-rows x 128 d-cols, halo 9 each side
// ---------------------------------------------------------------------------
__global__ void k_dwconv(const float* __restrict__ x) {
    const int b  = blockIdx.z;
    const int s0 = blockIdx.y * 32;
    const int d0 = blockIdx.x * 128;
    __shared__ float xs[50][128];
    __shared__ float ks[KS][128];
    const int tid = threadIdx.x;  // 256

    for (int i = tid; i < KS * 128; i += 256) {
        int t = i >> 7, d = i & 127;
        ks[t][d] = g_ksum[(d0 + d) * KS + t];
    }
    const float* xb = x + (size_t)b * Ss * Dd;
    for (int i = tid; i < 50 * 32; i += 256) {   // 32 float4 per row
        int r = i >> 5, c4 = (i & 31) * 4;
        int s = s0 - 9 + r;
        float4 v = make_float4(0.f, 0.f, 0.f, 0.f);
        if (s >= 0 && s < Ss) v = *(const float4*)(xb + (size_t)s * Dd + d0 + c4);
        *(float4*)&xs[r][c4] = v;
    }
    __syncthreads();

    const int d = tid & 127;
    const int sr0 = tid >> 7;     // 0 or 1
    #pragma unroll
    for (int j = 0; j < 16; j++) {
        int sr = sr0 + j * 2;
        float acc = 0.f;
        #pragma unroll
        for (int t = 0; t < KS; t++) acc = fmaf(xs[sr + t][d], ks[t][d], acc);
        g_pos[((size_t)b * Ss + s0 + sr) * Dd + d0 + d] = acc;
    }
}

// ---------------------------------------------------------------------------
// 3. SGEMM  C[M,N] = A[M,K] @ B[K,N]  (+ optional epilogue: + addX + bias)
//    128x128x16 tile, 256 threads, 8x8 per thread
// ---------------------------------------------------------------------------
template <int EPI_ADDX>
__global__ void k_sgemm(const float* __restrict__ A, const float* __restrict__ Bmat,
                        float* __restrict__ C, int M, int N, int K,
                        const float* __restrict__ addX, const float* __restrict__ bias) {
    __shared__ float As[16][128];
    __shared__ float Bs[16][128];
    const int bm = blockIdx.y * 128;
    const int bn = blockIdx.x * 128;
    const int tid = threadIdx.x;
    const int tx = tid & 15, ty = tid >> 4;

    float acc[8][8];
    #pragma unroll
    for (int i = 0; i < 8; i++)
        #pragma unroll
        for (int j = 0; j < 8; j++) acc[i][j] = 0.f;

    for (int k0 = 0; k0 < K; k0 += 16) {
        #pragma unroll
        for (int l = 0; l < 2; l++) {          // A tile: 128x16 -> transposed store
            int i  = tid + l * 256;
            int r  = i >> 2;
            int c4 = (i & 3) * 4;
            float4 v = *(const float4*)(A + (size_t)(bm + r) * K + k0 + c4);
            As[c4 + 0][r] = v.x; As[c4 + 1][r] = v.y;
            As[c4 + 2][r] = v.z; As[c4 + 3][r] = v.w;
        }
        #pragma unroll
        for (int l = 0; l < 2; l++) {          // B tile: 16x128
            int i  = tid + l * 256;
            int r  = i >> 5;
            int c4 = (i & 31) * 4;
            *(float4*)&Bs[r][c4] = *(const float4*)(Bmat + (size_t)(k0 + r) * N + bn + c4);
        }
        __syncthreads();
        #pragma unroll
        for (int kk = 0; kk < 16; kk++) {
            float a[8], b[8];
            #pragma unroll
            for (int i = 0; i < 8; i++) a[i] = As[kk][ty * 8 + i];
            #pragma unroll
            for (int i = 0; i < 8; i++) b[i] = Bs[kk][tx * 8 + i];
            #pragma unroll
            for (int i = 0; i < 8; i++)
                #pragma unroll
                for (int j = 0; j < 8; j++) acc[i][j] = fmaf(a[i], b[j], acc[i][j]);
        }
        __syncthreads();
    }

    #pragma unroll
    for (int i = 0; i < 8; i++) {
        const int row = bm + ty * 8 + i;
        #pragma unroll
        for (int j = 0; j < 8; j += 4) {
            const int col = bn + tx * 8 + j;
            float4 c = make_float4(acc[i][j], acc[i][j + 1], acc[i][j + 2], acc[i][j + 3]);
            if (EPI_ADDX) {
                float4 xv = *(const float4*)(addX + (size_t)row * N + col);
                float4 bv = *(const float4*)(bias + col);
                c.x += xv.x + bv.x; c.y += xv.y + bv.y;
                c.z += xv.z + bv.z; c.w += xv.w + bv.w;
            }
            *(float4*)(C + (size_t)row * N + col) = c;
        }
    }
}

// ---------------------------------------------------------------------------
// 4. LayerNorm in-place on g_y rows (512)
// ---------------------------------------------------------------------------
__global__ void k_layernorm(float* __restrict__ y,
                            const float* __restrict__ g, const float* __restrict__ b) {
    const int row = blockIdx.x;
    float* p = y + (size_t)row * Dd;
    const int tid = threadIdx.x;   // 256
    float2 v = ((float2*)p)[tid];
    float sum = v.x + v.y;
    float sq  = v.x * v.x + v.y * v.y;
    #pragma unroll
    for (int o = 16; o; o >>= 1) {
        sum += __shfl_xor_sync(~0u, sum, o);
        sq  += __shfl_xor_sync(~0u, sq, o);
    }
    __shared__ float rs[8], rq[8];
    __shared__ float s_m, s_r;
    if ((tid & 31) == 0) { rs[tid >> 5] = sum; rq[tid >> 5] = sq; }
    __syncthreads();
    if (tid == 0) {
        float s = 0.f, q = 0.f;
        #pragma unroll
        for (int i = 0; i < 8; i++) { s += rs[i]; q += rq[i]; }
        float m = s / Dd;
        float var = q / Dd - m * m;
        s_m = m; s_r = rsqrtf(var + 1e-5f);
    }
    __syncthreads();
    const float m = s_m, r = s_r;
    float2 gv = ((const float2*)g)[tid];
    float2 bv = ((const float2*)b)[tid];
    v.x = (v.x - m) * r * gv.x + bv.x;
    v.y = (v.y - m) * r * gv.y + bv.y;
    ((float2*)p)[tid] = v;
}

// ---------------------------------------------------------------------------
// 5. q = cls_token @ Wq    (batch-independent; [2, 512])
// ---------------------------------------------------------------------------
__global__ void k_q(const float* __restrict__ cls, const float* __restrict__ Wq) {
    int idx = blockIdx.x * blockDim.x + threadIdx.x;   // 0..1023
    int n = idx >> 9, j = idx & 511;
    float acc = 0.f;
    #pragma unroll 4
    for (int d = 0; d < Dd; d++) acc = fmaf(cls[n * Dd + d], Wq[(size_t)d * Dd + j], acc);
    g_q[n * Dd + j] = acc;
}

// ---------------------------------------------------------------------------
// 6. attention: scores->sigmoid->attn (to output) and o = attn @ v
//    block per (b,h); 8 warps x 256 contiguous s each; warp-shuffle dot
// ---------------------------------------------------------------------------
__global__ void k_attn(float* __restrict__ out_attn) {
    const int b = blockIdx.x >> 4;
    const int h = blockIdx.x & 15;
    const int tid = threadIdx.x;        // 256
    const int warp = tid >> 5, lane = tid & 31;
    __shared__ float qs[2][32];
    if (tid < 64) qs[tid >> 5][tid & 31] = g_q[(tid >> 5) * Dd + h * HDd + (tid & 31)];
    __syncthreads();
    const float q0 = qs[0][lane], q1 = qs[1][lane];
    const float scale = 0.17677669529663687f;   // 1/sqrt(32)
    const float logS  = 7.6246189861593985f;    // log(2048)
    float o0 = 0.f, o1 = 0.f;
    const float* kvb = g_kv + (size_t)b * Ss * 1024 + h * HDd;
    float* a0p = out_attn + (((size_t)b * Hh + h) * NCLS + 0) * Ss;
    float* a1p = a0p + Ss;

    const int sEnd = warp * 256 + 256;
    for (int s = warp * 256; s < sEnd; s++) {
        const float* kp = kvb + (size_t)s * 1024;
        float kx = kp[lane];
        float vx = kp[512 + lane];
        float d0 = q0 * kx, d1 = q1 * kx;
        #pragma unroll
        for (int o = 16; o; o >>= 1) {
            d0 += __shfl_xor_sync(~0u, d0, o);
            d1 += __shfl_xor_sync(~0u, d1, o);
        }
        float a0 = 1.f / (1.f + expf(-(d0 * scale - logS)));
        float a1 = 1.f / (1.f + expf(-(d1 * scale - logS)));
        o0 = fmaf(a0, vx, o0);
        o1 = fmaf(a1, vx, o1);
        if (lane == 0) a0p[s] = a0;
        if (lane == 1) a1p[s] = a1;
    }
    __shared__ float osh[8][2][32];
    osh[warp][0][lane] = o0;
    osh[warp][1][lane] = o1;
    __syncthreads();
    if (tid < 64) {
        int n = tid >> 5, l = tid & 31;
        float acc = 0.f;
        #pragma unroll
        for (int w = 0; w < 8; w++) acc += osh[w][n][l];
        g_o[((size_t)b * NCLS + n) * Dd + h * HDd + l] = acc;
    }
}

// ---------------------------------------------------------------------------
// 7. head: per row r=b*2+n: p = o@Wproj+bproj; LN; h=relu(p@Wc1+bc1);
//    logit = h@Wc2 + bc2
// ---------------------------------------------------------------------------
__global__ void k_head(const float* __restrict__ Wproj, const float* __restrict__ bproj,
                       const float* __restrict__ ln2g, const float* __restrict__ ln2b,
                       const float* __restrict__ Wc1, const float* __restrict__ bc1,
                       const float* __restrict__ Wc2, const float* __restrict__ bc2,
                       float* __restrict__ logits) {
    const int r = blockIdx.x;
    const int tid = threadIdx.x;  // 256
    __shared__ float orow[Dd];
    __shared__ float prow[Dd];
    __shared__ float rs[8], rq[8];
    __shared__ float s_m, s_r;
    orow[tid]       = g_o[r * Dd + tid];
    orow[tid + 256] = g_o[r * Dd + tid + 256];
    __syncthreads();

    float pv[2];
    #pragma unroll
    for (int l = 0; l < 2; l++) {
        int j = tid + l * 256;
        float acc = bproj[j];
        #pragma unroll 4
        for (int d = 0; d < Dd; d++) acc = fmaf(orow[d], Wproj[(size_t)d * Dd + j], acc);
        pv[l] = acc;
    }
    float sum = pv[0] + pv[1];
    float sq  = pv[0] * pv[0] + pv[1] * pv[1];
    #pragma unroll
    for (int o = 16; o; o >>= 1) {
        sum += __shfl_xor_sync(~0u, sum, o);
        sq  += __shfl_xor_sync(~0u, sq, o);
    }
    if ((tid & 31) == 0) { rs[tid >> 5] = sum; rq[tid >> 5] = sq; }
    __syncthreads();
    if (tid == 0) {
        float s = 0.f, q = 0.f;
        #pragma unroll
        for (int i = 0; i < 8; i++) { s += rs[i]; q += rq[i]; }
        float m = s / Dd;
        float v = q / Dd - m * m;
        s_m = m; s_r = rsqrtf(v + 1e-5f);
    }
    __syncthreads();
    #pragma unroll
    for (int l = 0; l < 2; l++) {
        int j = tid + l * 256;
        prow[j] = (pv[l] - s_m) * s_r * ln2g[j] + ln2b[j];
    }
    __syncthreads();

    float part = 0.f;
    #pragma unroll
    for (int l = 0; l < 2; l++) {
        int j = tid + l * 256;
        float acc = bc1[j];
        #pragma unroll 4
        for (int d = 0; d < Dd; d++) acc = fmaf(prow[d], Wc1[(size_t)d * Dd + j], acc);
        acc = fmaxf(acc, 0.f);
        part = fmaf(acc, Wc2[j], part);
    }
    #pragma unroll
    for (int o = 16; o; o >>= 1) part += __shfl_xor_sync(~0u, part, o);
    if ((tid & 31) == 0) rs[tid >> 5] = part;
    __syncthreads();
    if (tid == 0) {
        float s = 0.f;
        #pragma unroll
        for (int i = 0; i < 8; i++) s += rs[i];
        logits[r] = s + bc2[0];
    }
}

// ---------------------------------------------------------------------------
extern "C" void kernel_launch(void* const* d_in, const int* in_sizes, int n_in,
                              void* d_out, int out_size) {
    const float* x      = (const float*)d_in[0];
    const float* wave1  = (const float*)d_in[1];
    const float* wave2  = (const float*)d_in[2];
    const float* wave3  = (const float*)d_in[3];
    const float* Wp1    = (const float*)d_in[4];
    const float* bp1    = (const float*)d_in[5];
    const float* cls    = (const float*)d_in[6];
    const float* ln1g   = (const float*)d_in[7];
    const float* ln1b   = (const float*)d_in[8];
    const float* Wq     = (const float*)d_in[9];
    const float* Wkv    = (const float*)d_in[10];
    const float* Wproj  = (const float*)d_in[11];
    const float* bproj  = (const float*)d_in[12];
    const float* ln2g   = (const float*)d_in[13];
    const float* ln2b   = (const float*)d_in[14];
    const float* Wc1    = (const float*)d_in[15];
    const float* bc1    = (const float*)d_in[16];
    const float* Wc2    = (const float*)d_in[17];
    const float* bc2    = (const float*)d_in[18];

    float* out = (float*)d_out;           // [0,64) logits, [64, ...) attn
    float* out_attn = out + Bb * NCLS;

    float* pos; cudaGetSymbolAddress((void**)&pos, g_pos);
    float* y;   cudaGetSymbolAddress((void**)&y,   g_y);
    float* kv;  cudaGetSymbolAddress((void**)&kv,  g_kv);

    // 1. summed wavelet kernel
    k_wavelet<<<1, 512>>>(wave1, wave2, wave3);
    // 2. depthwise conv -> g_pos
    k_dwconv<<<dim3(Dd / 128, Ss / 32, Bb), 256>>>(x);
    // 5. q (independent; overlapped)
    k_q<<<4, 256>>>(cls, Wq);
    // 3. y = pos @ Wp1 + x + bp1
    k_sgemm<1><<<dim3(Dd / 128, Mm / 128), 256>>>(pos, Wp1, y, Mm, Dd, Dd, x, bp1);
    // 4. xn = LN(y) in place
    k_layernorm<<<Mm, 256>>>(y, ln1g, ln1b);
    // kv = xn @ Wkv
    k_sgemm<0><<<dim3(2 * Dd / 128, Mm / 128), 256>>>(y, Wkv, kv, Mm, 2 * Dd, Dd,
                                                      nullptr, nullptr);
    // 6. attention + attn output + o
    k_attn<<<Bb * Hh, 256>>>(out_attn);
    // 7. head -> logits
    k_head<<<Bb * NCLS, 256>>>(Wproj, bproj, ln2g, ln2b, Wc1, bc1, Wc2, bc2, out);
}